// round 8
// baseline (speedup 1.0000x reference)
#include <cuda_runtime.h>
#include <cuda_bf16.h>

#define BB 2
#define NN 64
#define NGTK 8
#define CC 17
#define HWSZ 4096
#define S_TILES 16
#define TILE (HWSZ / S_TILES)   /* 256 */
#define TP2 (TILE / 2)          /* 128 float2-pairs per tile */

// Scratch (device globals — no runtime allocation allowed).
// Every slot is written every call (plain stores) -> no zeroing needed.
__device__ float g_part[BB * NN * NGTK * CC * S_TILES];   // [b][n][g][c][s]
__device__ int   g_pkmask[BB * CC * S_TILES];             // [b][c][s] -> 8-bit g mask

// ---------------------------------------------------------------------------
// A2 = softplus(x)*p^2 ; nX2 = -(x*p^2),  p = sigmoid(x)
__device__ __forceinline__ void ph_pre(float x, float& A2, float& nX2) {
    float e  = __expf(-fabsf(x));
    float r  = __fdividef(1.0f, 1.0f + e);
    float p  = (x >= 0.0f) ? r : 1.0f - r;          // sigmoid(x)
    float a  = fmaxf(x, 0.0f) + __logf(1.0f + e);   // softplus(x)
    float p2 = p * p;
    A2  = a * p2;
    nX2 = -(x * p2);
}

// Dense focal-cost accumulation, UNMASKED (valid applied in finalize),
// with local peak detection (t == 1.0 can only be a kept peak).
// grid = (S_TILES, CC, BB), 256 threads (8 warps), 4 blocks/SM -> single wave.
__global__ __launch_bounds__(256, 4) void dense_kernel(const float* __restrict__ ph,
                                                       const float* __restrict__ gt) {
    int s = blockIdx.x, c = blockIdx.y, b = blockIdx.z;
    int tid = threadIdx.x;

    __shared__ float4 sg[NGTK][TP2];   // (c2_e, c2_o, d2_e, d2_o) per pair — 16 KB
    __shared__ int s_pke[NGTK];        // local peak element offset within tile, or -1

    if (tid < NGTK) s_pke[tid] = -1;
    __syncthreads();

    // fill smem from gt: c2 = (1-t)^4, d2 = t*c2 ; detect t==1.0 peaks
#pragma unroll
    for (int pass = 0; pass < 2; ++pass) {
        int g  = pass * 4 + (tid >> 6);
        int q4 = tid & 63;                       // float4 index within tile
        const float4* gsrc = reinterpret_cast<const float4*>(
            gt + ((size_t)(b * NGTK + g) * CC + c) * HWSZ + (size_t)s * TILE);
        float4 tv = gsrc[q4];
        int base = q4 * 4;
        if (tv.x == 1.0f) s_pke[g] = base;
        if (tv.y == 1.0f) s_pke[g] = base + 1;
        if (tv.z == 1.0f) s_pke[g] = base + 2;
        if (tv.w == 1.0f) s_pke[g] = base + 3;
        float o0 = 1.0f - tv.x, o1 = 1.0f - tv.y, o2 = 1.0f - tv.z, o3 = 1.0f - tv.w;
        float w0 = o0 * o0, w1 = o1 * o1, w2 = o2 * o2, w3 = o3 * o3;
        float c0 = w0 * w0, c1 = w1 * w1, c2v = w2 * w2, c3 = w3 * w3;
        sg[g][2 * q4]     = make_float4(c0,  c1, tv.x * c0,  tv.y * c1);
        sg[g][2 * q4 + 1] = make_float4(c2v, c3, tv.z * c2v, tv.w * c3);
    }
    __syncthreads();

    // packed validity mask for this (b,c,s): bit g set iff peak in this tile
    if (tid < 32) {
        bool flag = (tid < NGTK) && (s_pke[tid] >= 0);
        unsigned m = __ballot_sync(0xffffffffu, flag) & 0xFFu;
        if (tid == 0) g_pkmask[(b * CC + c) * S_TILES + s] = (int)m;
    }

    int w = tid >> 5, L = tid & 31;
    const float* phb = ph + ((size_t)(b * NN) * CC + c) * HWSZ + (size_t)s * TILE;

#pragma unroll
    for (int rep = 0; rep < 2; ++rep) {
        int n0 = w * 8 + rep * 4;

        const float2* pp[4];
#pragma unroll
        for (int u = 0; u < 4; u++)
            pp[u] = reinterpret_cast<const float2*>(phb + (size_t)(n0 + u) * CC * HWSZ);

        float acc[32];   // acc[u*8+g]
#pragma unroll
        for (int k = 0; k < 32; k++) acc[k] = 0.0f;

        float2 xv[4];
#pragma unroll
        for (int u = 0; u < 4; u++) xv[u] = __ldcs(&pp[u][L]);

#pragma unroll
        for (int i = 0; i < TP2 / 32; i++) {     // 4 iterations
            int ep = L + 32 * i;
            float2 nxt[4];
            if (i < TP2 / 32 - 1) {
#pragma unroll
                for (int u = 0; u < 4; u++) nxt[u] = __ldcs(&pp[u][ep + 32]);
            }
            float A2[4][2], nX2[4][2];
#pragma unroll
            for (int u = 0; u < 4; u++) {
                ph_pre(xv[u].x, A2[u][0], nX2[u][0]);
                ph_pre(xv[u].y, A2[u][1], nX2[u][1]);
            }
#pragma unroll
            for (int g = 0; g < NGTK; g++) {
                float4 ct = sg[g][ep];
#pragma unroll
                for (int u = 0; u < 4; u++) {
                    float t = acc[u * 8 + g];
                    t = fmaf(A2[u][0],  ct.x, t);
                    t = fmaf(nX2[u][0], ct.z, t);
                    t = fmaf(A2[u][1],  ct.y, t);
                    t = fmaf(nX2[u][1], ct.w, t);
                    acc[u * 8 + g] = t;
                }
            }
#pragma unroll
            for (int u = 0; u < 4; u++) xv[u] = nxt[u];
        }

        // peak correction: lane L < 8 handles gt g = L (peak in this tile only);
        // added pre-reduction on one lane, summed by the tree like everything else
        if (L < NGTK) {
            int pk = s_pke[L];
            if (pk >= 0) {
#pragma unroll
                for (int u = 0; u < 4; u++) {
                    float x = phb[(size_t)(n0 + u) * CC * HWSZ + pk];
                    float e = __expf(-fabsf(x));
                    float r = __fdividef(1.0f, 1.0f + e);
                    float p = (x >= 0.0f) ? r : 1.0f - r;
                    float a = fmaxf(x, 0.0f) + __logf(1.0f + e);
                    float q = 1.0f - p;
                    acc[u * 8 + L] += (a - x) * q * q;   // ce * (1-p)^2 at t==1
                }
            }
        }

        // logarithmic multi-value warp reduction:
        // after the tree, lane L holds full sum of value idx = bitrev5(L)
#pragma unroll
        for (int o = 1, m = 32; o <= 16; o <<= 1, m >>= 1) {
            int h = m >> 1;
            bool hiL = (L & o) != 0;
#pragma unroll
            for (int j = 0; j < 16; j++) {
                if (j < h) {
                    float send = hiL ? acc[j] : acc[j + h];
                    float keep = hiL ? acc[j + h] : acc[j];
                    acc[j] = keep + __shfl_xor_sync(0xffffffffu, send, o);
                }
            }
        }
        int idx = ((L & 1) << 4) | ((L & 2) << 2) | (L & 4) | ((L & 8) >> 2) | ((L & 16) >> 4);
        int u = idx >> 3, g = idx & 7;
        g_part[(((size_t)(b * NN + n0 + u) * NGTK + g) * CC + c) * S_TILES + s] = acc[0];
    }
}

// ---------------------------------------------------------------------------
__device__ __forceinline__ float fast_sigmoid(float x) {
    float e = __expf(-fabsf(x));
    float r = __fdividef(1.0f, 1.0f + e);
    return (x >= 0.0f) ? r : 1.0f - r;
}

// grid = BB*NN blocks x 256 threads; warp g of block (b,n) produces out[b,n,g].
// Deferred masking: raw partial loads and mask loads run concurrently.
__global__ void finalize_kernel(const float* __restrict__ ps,
                                const float* __restrict__ po,
                                const float* __restrict__ go,
                                float* __restrict__ out) {
    __shared__ int   s_maskc[CC];      // OR over s of packed g-masks, per c
    __shared__ float s_vcnt[NGTK];
    int t = threadIdx.x;
    int bn = blockIdx.x;            // 0..127
    int b = bn >> 6;
    int g = t >> 5, L = t & 31;

    if (t < CC) s_maskc[t] = 0;

    // stream 1: mask loads — 68 threads needed (CC*4), window [188, 256)
    int4 mv = make_int4(0, 0, 0, 0);
    int mc = -1;
    if (t >= 188) {                       // 188 + CC*4 == 256 exactly
        int i = t - 188;
        mc = i >> 2;
        int quad = i & 3;
        mv = *reinterpret_cast<const int4*>(&g_pkmask[(b * CC + mc) * S_TILES + quad * 4]);
    }

    // stream 2: raw partial loads (independent of masks)
    const float* base = &g_part[(((size_t)bn * NGTK + g) * CC) * S_TILES];
    float rc[9];
#pragma unroll
    for (int j = 0; j < 9; j++) {
        int idx = L + 32 * j;
        rc[j] = (idx < CC * S_TILES) ? base[idx] : 0.0f;
    }

    // stream 3: offset-cost raw terms (masked later)
    float offraw = 0.0f;
    if (L < CC) {
        float2 pov = *reinterpret_cast<const float2*>(po + ((size_t)bn * CC + L) * 2);
        float2 gov = *reinterpret_cast<const float2*>(go + ((size_t)(b * NGTK + g) * CC + L) * 2);
        float s0 = fast_sigmoid(pov.x) - gov.x;
        float s1 = fast_sigmoid(pov.y) - gov.y;
        offraw = 0.5f * (s0 * s0 + s1 * s1);
    }

    __syncthreads();
    if (mc >= 0) atomicOr(&s_maskc[mc], (mv.x | mv.y) | (mv.z | mv.w));
    __syncthreads();
    if (t < NGTK) {
        float cnt = 0.0f;
#pragma unroll
        for (int c = 0; c < CC; c++) cnt += (float)((s_maskc[c] >> t) & 1);
        s_vcnt[t] = cnt;
    }
    __syncthreads();

    // combine with masks
    float r = 0.0f;
#pragma unroll
    for (int j = 0; j < 9; j++) {
        int idx = L + 32 * j;
        if (idx < CC * S_TILES) {
            int c = idx >> 4;              // S_TILES == 16
            float v = (float)((s_maskc[c] >> g) & 1);
            r += 2.0f * v * rc[j];         // HMS_W=2 folded in
        }
    }
    if (L < CC) {
        float v = (float)((s_maskc[L] >> g) & 1);
        r += v * offraw;                   // OFF_W/2 already folded
    }
#pragma unroll
    for (int o = 16; o > 0; o >>= 1)
        r += __shfl_xor_sync(0xffffffffu, r, o);

    if (L == 0) {
        float nk = fmaxf(s_vcnt[g], 1.0f);
        // score cost: ALPHA * bce(x,1) * (1-sigmoid(x))^2
        float x = ps[bn];
        float e = __expf(-fabsf(x));
        float rr = __fdividef(1.0f, 1.0f + e);
        float sp = (x >= 0.0f) ? rr : 1.0f - rr;
        float bce1 = fmaxf(x, 0.0f) - x + __logf(1.0f + e);
        float q = 1.0f - sp;
        float ssc = 0.25f * bce1 * q * q;
        out[bn * NGTK + g] = __fdividef(r, nk) + ssc;
    }
}

// ---------------------------------------------------------------------------
extern "C" void kernel_launch(void* const* d_in, const int* in_sizes, int n_in,
                              void* d_out, int out_size) {
    const float *ph = nullptr, *gt = nullptr, *ps = nullptr, *po = nullptr, *go = nullptr;
    for (int i = 0; i < n_in; i++) {
        switch (in_sizes[i]) {
            case BB * NN * CC * HWSZ:   ph = (const float*)d_in[i]; break;  // 8,912,896
            case BB * NGTK * CC * HWSZ: gt = (const float*)d_in[i]; break;  // 1,114,112
            case BB * NN:               ps = (const float*)d_in[i]; break;  // 128
            case BB * NN * CC * 2:      po = (const float*)d_in[i]; break;  // 4,352
            case BB * NGTK * CC * 2:    go = (const float*)d_in[i]; break;  // 544
            default: break;
        }
    }
    float* out = (float*)d_out;

    dense_kernel<<<dim3(S_TILES, CC, BB), 256>>>(ph, gt);
    finalize_kernel<<<BB * NN, 256>>>(ps, po, go, out);
}

// round 9
// speedup vs baseline: 1.1454x; 1.1454x over previous
#include <cuda_runtime.h>
#include <cuda_bf16.h>

#define BB 2
#define NN 64
#define NGTK 8
#define CC 17
#define HWSZ 4096
#define S_TILES 16
#define TILE (HWSZ / S_TILES)   /* 256 */
#define TP2 (TILE / 2)          /* 128 element-pairs per tile */

// Scratch (device globals — no runtime allocation allowed).
// Every slot is written every call (plain stores) -> no zeroing needed.
__device__ float g_part[BB * NN * NGTK * CC * S_TILES];   // [b][n][g][c][s]
__device__ int   g_pkmask[BB * CC * S_TILES];             // [b][c][s] -> 8-bit g mask

// ---------------------------------------------------------------------------
// A2 = softplus(x)*p^2 ; nX2 = -(x*p^2),  p = sigmoid(x)
__device__ __forceinline__ void ph_pre(float x, float& A2, float& nX2) {
    float e  = __expf(-fabsf(x));
    float r  = __fdividef(1.0f, 1.0f + e);
    float p  = (x >= 0.0f) ? r : 1.0f - r;          // sigmoid(x)
    float a  = fmaxf(x, 0.0f) + __logf(1.0f + e);   // softplus(x)
    float p2 = p * p;
    A2  = a * p2;
    nX2 = -(x * p2);
}

// Dense focal-cost accumulation, UNMASKED (valid applied in finalize),
// with local peak detection (t == 1.0 can only be a kept peak).
// grid = (S_TILES, CC, BB), 256 threads (8 warps), 4 blocks/SM -> single wave.
// Warp w, rep r (0..3): preds n = w*8 + r*2 + u, u in {0,1}. acc[16] only.
__global__ __launch_bounds__(256, 4) void dense_kernel(const float* __restrict__ ph,
                                                       const float* __restrict__ gt) {
    int s = blockIdx.x, c = blockIdx.y, b = blockIdx.z;
    int tid = threadIdx.x;

    __shared__ float4 sg[NGTK][TP2];   // (c2_e, c2_o, d2_e, d2_o) per pair — 16 KB
    __shared__ int s_pke[NGTK];        // local peak element offset within tile, or -1

    if (tid < NGTK) s_pke[tid] = -1;
    __syncthreads();

    // fill smem from gt: c2 = (1-t)^4, d2 = t*c2 ; detect t==1.0 peaks
#pragma unroll
    for (int pass = 0; pass < 2; ++pass) {
        int g  = pass * 4 + (tid >> 6);
        int q4 = tid & 63;                       // float4 index within tile
        const float4* gsrc = reinterpret_cast<const float4*>(
            gt + ((size_t)(b * NGTK + g) * CC + c) * HWSZ + (size_t)s * TILE);
        float4 tv = gsrc[q4];
        int base = q4 * 4;
        if (tv.x == 1.0f) s_pke[g] = base;
        if (tv.y == 1.0f) s_pke[g] = base + 1;
        if (tv.z == 1.0f) s_pke[g] = base + 2;
        if (tv.w == 1.0f) s_pke[g] = base + 3;
        float o0 = 1.0f - tv.x, o1 = 1.0f - tv.y, o2 = 1.0f - tv.z, o3 = 1.0f - tv.w;
        float w0 = o0 * o0, w1 = o1 * o1, w2 = o2 * o2, w3 = o3 * o3;
        float c0 = w0 * w0, c1 = w1 * w1, c2v = w2 * w2, c3 = w3 * w3;
        sg[g][2 * q4]     = make_float4(c0,  c1, tv.x * c0,  tv.y * c1);
        sg[g][2 * q4 + 1] = make_float4(c2v, c3, tv.z * c2v, tv.w * c3);
    }
    __syncthreads();

    // packed validity mask for this (b,c,s): bit g set iff peak in this tile
    if (tid < 32) {
        bool flag = (tid < NGTK) && (s_pke[tid] >= 0);
        unsigned m = __ballot_sync(0xffffffffu, flag) & 0xFFu;
        if (tid == 0) g_pkmask[(b * CC + c) * S_TILES + s] = (int)m;
    }

    int w = tid >> 5, L = tid & 31;
    const float* phb = ph + ((size_t)(b * NN) * CC + c) * HWSZ + (size_t)s * TILE;

#pragma unroll
    for (int rep = 0; rep < 4; ++rep) {
        int n0 = w * 8 + rep * 2;

        const float2* pp[2];
#pragma unroll
        for (int u = 0; u < 2; u++)
            pp[u] = reinterpret_cast<const float2*>(phb + (size_t)(n0 + u) * CC * HWSZ);

        float acc[16];   // acc[u*8+g], u in {0,1}
#pragma unroll
        for (int k = 0; k < 16; k++) acc[k] = 0.0f;

        float2 xv[2];
#pragma unroll
        for (int u = 0; u < 2; u++) xv[u] = __ldcs(&pp[u][L]);

#pragma unroll
        for (int i = 0; i < TP2 / 32; i++) {     // 4 iterations
            int ep = L + 32 * i;
            float2 nxt[2];
            if (i < TP2 / 32 - 1) {
#pragma unroll
                for (int u = 0; u < 2; u++) nxt[u] = __ldcs(&pp[u][ep + 32]);
            }
            float A2[2][2], nX2[2][2];
#pragma unroll
            for (int u = 0; u < 2; u++) {
                ph_pre(xv[u].x, A2[u][0], nX2[u][0]);
                ph_pre(xv[u].y, A2[u][1], nX2[u][1]);
            }
#pragma unroll
            for (int g = 0; g < NGTK; g++) {
                float4 ct = sg[g][ep];
#pragma unroll
                for (int u = 0; u < 2; u++) {
                    float t = acc[u * 8 + g];
                    t = fmaf(A2[u][0],  ct.x, t);
                    t = fmaf(nX2[u][0], ct.z, t);
                    t = fmaf(A2[u][1],  ct.y, t);
                    t = fmaf(nX2[u][1], ct.w, t);
                    acc[u * 8 + g] = t;
                }
            }
#pragma unroll
            for (int u = 0; u < 2; u++) xv[u] = nxt[u];
        }

        // peak correction: lane L < 8 handles gt g = L (peak in this tile only)
        if (L < NGTK) {
            int pk = s_pke[L];
            if (pk >= 0) {
#pragma unroll
                for (int u = 0; u < 2; u++) {
                    float x = phb[(size_t)(n0 + u) * CC * HWSZ + pk];
                    float e = __expf(-fabsf(x));
                    float r = __fdividef(1.0f, 1.0f + e);
                    float p = (x >= 0.0f) ? r : 1.0f - r;
                    float a = fmaxf(x, 0.0f) + __logf(1.0f + e);
                    float q = 1.0f - p;
                    acc[u * 8 + L] += (a - x) * q * q;   // ce * (1-p)^2 at t==1
                }
            }
        }

        // logarithmic multi-value warp reduction for V=16:
        // 4 levels halve value count; final fold at offset 16 completes the sum.
#pragma unroll
        for (int o = 1, m = 16; o <= 8; o <<= 1, m >>= 1) {
            int h = m >> 1;
            bool hiL = (L & o) != 0;
#pragma unroll
            for (int j = 0; j < 8; j++) {
                if (j < h) {
                    float send = hiL ? acc[j] : acc[j + h];
                    float keep = hiL ? acc[j + h] : acc[j];
                    acc[j] = keep + __shfl_xor_sync(0xffffffffu, send, o);
                }
            }
        }
        acc[0] += __shfl_xor_sync(0xffffffffu, acc[0], 16);
        // lane L (< 16) holds value idx = bitrev4(L): u = idx>>3, g = idx&7
        if (L < 16) {
            int idx = ((L & 1) << 3) | ((L & 2) << 1) | ((L & 4) >> 1) | ((L & 8) >> 3);
            int u = idx >> 3, g = idx & 7;
            g_part[(((size_t)(b * NN + n0 + u) * NGTK + g) * CC + c) * S_TILES + s] = acc[0];
        }
    }
}

// ---------------------------------------------------------------------------
__device__ __forceinline__ float fast_sigmoid(float x) {
    float e = __expf(-fabsf(x));
    float r = __fdividef(1.0f, 1.0f + e);
    return (x >= 0.0f) ? r : 1.0f - r;
}

// grid = BB*NN blocks x 256 threads; warp g of block (b,n) produces out[b,n,g].
// Deferred masking: raw partial loads and mask loads run concurrently.
__global__ void finalize_kernel(const float* __restrict__ ps,
                                const float* __restrict__ po,
                                const float* __restrict__ go,
                                float* __restrict__ out) {
    __shared__ int   s_maskc[CC];      // OR over s of packed g-masks, per c
    __shared__ float s_vcnt[NGTK];
    int t = threadIdx.x;
    int bn = blockIdx.x;            // 0..127
    int b = bn >> 6;
    int g = t >> 5, L = t & 31;

    if (t < CC) s_maskc[t] = 0;

    // stream 1: mask loads — 68 threads needed (CC*4), window [188, 256)
    int4 mv = make_int4(0, 0, 0, 0);
    int mc = -1;
    if (t >= 188) {                       // 188 + CC*4 == 256 exactly
        int i = t - 188;
        mc = i >> 2;
        int quad = i & 3;
        mv = *reinterpret_cast<const int4*>(&g_pkmask[(b * CC + mc) * S_TILES + quad * 4]);
    }

    // stream 2: raw partial loads (independent of masks)
    const float* base = &g_part[(((size_t)bn * NGTK + g) * CC) * S_TILES];
    float rc[9];
#pragma unroll
    for (int j = 0; j < 9; j++) {
        int idx = L + 32 * j;
        rc[j] = (idx < CC * S_TILES) ? base[idx] : 0.0f;
    }

    // stream 3: offset-cost raw terms (masked later)
    float offraw = 0.0f;
    if (L < CC) {
        float2 pov = *reinterpret_cast<const float2*>(po + ((size_t)bn * CC + L) * 2);
        float2 gov = *reinterpret_cast<const float2*>(go + ((size_t)(b * NGTK + g) * CC + L) * 2);
        float s0 = fast_sigmoid(pov.x) - gov.x;
        float s1 = fast_sigmoid(pov.y) - gov.y;
        offraw = 0.5f * (s0 * s0 + s1 * s1);
    }

    __syncthreads();
    if (mc >= 0) atomicOr(&s_maskc[mc], (mv.x | mv.y) | (mv.z | mv.w));
    __syncthreads();
    if (t < NGTK) {
        float cnt = 0.0f;
#pragma unroll
        for (int c = 0; c < CC; c++) cnt += (float)((s_maskc[c] >> t) & 1);
        s_vcnt[t] = cnt;
    }
    __syncthreads();

    // combine with masks
    float r = 0.0f;
#pragma unroll
    for (int j = 0; j < 9; j++) {
        int idx = L + 32 * j;
        if (idx < CC * S_TILES) {
            int c = idx >> 4;              // S_TILES == 16
            float v = (float)((s_maskc[c] >> g) & 1);
            r += 2.0f * v * rc[j];         // HMS_W=2 folded in
        }
    }
    if (L < CC) {
        float v = (float)((s_maskc[L] >> g) & 1);
        r += v * offraw;                   // OFF_W/2 already folded
    }
#pragma unroll
    for (int o = 16; o > 0; o >>= 1)
        r += __shfl_xor_sync(0xffffffffu, r, o);

    if (L == 0) {
        float nk = fmaxf(s_vcnt[g], 1.0f);
        // score cost: ALPHA * bce(x,1) * (1-sigmoid(x))^2
        float x = ps[bn];
        float e = __expf(-fabsf(x));
        float rr = __fdividef(1.0f, 1.0f + e);
        float sp = (x >= 0.0f) ? rr : 1.0f - rr;
        float bce1 = fmaxf(x, 0.0f) - x + __logf(1.0f + e);
        float q = 1.0f - sp;
        float ssc = 0.25f * bce1 * q * q;
        out[bn * NGTK + g] = __fdividef(r, nk) + ssc;
    }
}

// ---------------------------------------------------------------------------
extern "C" void kernel_launch(void* const* d_in, const int* in_sizes, int n_in,
                              void* d_out, int out_size) {
    const float *ph = nullptr, *gt = nullptr, *ps = nullptr, *po = nullptr, *go = nullptr;
    for (int i = 0; i < n_in; i++) {
        switch (in_sizes[i]) {
            case BB * NN * CC * HWSZ:   ph = (const float*)d_in[i]; break;  // 8,912,896
            case BB * NGTK * CC * HWSZ: gt = (const float*)d_in[i]; break;  // 1,114,112
            case BB * NN:               ps = (const float*)d_in[i]; break;  // 128
            case BB * NN * CC * 2:      po = (const float*)d_in[i]; break;  // 4,352
            case BB * NGTK * CC * 2:    go = (const float*)d_in[i]; break;  // 544
            default: break;
        }
    }
    float* out = (float*)d_out;

    dense_kernel<<<dim3(S_TILES, CC, BB), 256>>>(ph, gt);
    finalize_kernel<<<BB * NN, 256>>>(ps, po, go, out);
}